// round 9
// baseline (speedup 1.0000x reference)
#include <cuda_runtime.h>
#include <cstdint>

// Problem constants (fixed by the dataset)
#define B_   8
#define T_   1024
#define CIN_ 4096
#define CH_  4096
#define NW_  (CH_/32)      // 128 words per hidden state

// Scratch (device globals: no allocation allowed)
__device__ int           g_in_idx [CH_ * 3];               // fan-in of input graph
__device__ int           g_hid_idx[CH_ * 3];               // fan-in of hidden graph
__device__ unsigned char g_inor[(size_t)B_ * T_ * CH_];    // 33.5 MB byte input_or
__device__ unsigned      g_hsp [B_ * T_ * NW_];            // 4 MB bit-packed h sequence

// ---------------------------------------------------------------------------
// K1: extract the 3 nonzero column indices per row. One WARP per row,
// ballot + ffs compaction. Nonzero test is on the raw 32-bit WORD, which is
// correct whether the matrix is float32 (1.0f = 0x3F800000) or int32 (1).
// grid = 1024 x 256 = 8192 warps (4096 input + 4096 hidden rows).
// ---------------------------------------------------------------------------
__global__ void __launch_bounds__(256) extract_idx_kernel(
    const unsigned* __restrict__ Ain, const unsigned* __restrict__ Ahid)
{
    int wg   = (blockIdx.x * 256 + threadIdx.x) >> 5;
    int lane = threadIdx.x & 31;

    const unsigned* row;
    int* outp;
    if (wg < CH_) { row = Ain  + (size_t)wg * CIN_;         outp = g_in_idx  + 3 * wg; }
    else          { row = Ahid + (size_t)(wg - CH_) * CH_;  outp = g_hid_idx + 3 * (wg - CH_); }

    int cnt = 0;
#pragma unroll 4
    for (int base = 0; base < CIN_; base += 32) {
        unsigned v = row[base + lane];
        unsigned m = __ballot_sync(0xffffffffu, v != 0u);
        while (m != 0u && cnt < 3) {
            int bit = __ffs(m) - 1;
            if (lane == 0) outp[cnt] = base + bit;
            cnt++;
            m &= m - 1u;
        }
        if (cnt >= 3) break;   // cnt is warp-uniform
    }
}

// ---------------------------------------------------------------------------
// K2: per time step t (grid = T_ blocks, 1024 threads):
//   (a) write z into the output as explicit 1.0f/0.0f floats (dtype fix!)
//   (b) stage z as 0/1 BYTES in smem (nonzero test on raw words)
//   (c) gather: g_inor[b][t][i] = z[a0(i)] | z[a1(i)] | z[a2(i)]  (bytes)
// ---------------------------------------------------------------------------
__global__ void __launch_bounds__(1024) input_or_kernel(
    const uint4* __restrict__ z, float* __restrict__ out)
{
    __shared__ unsigned char zs[B_ * CIN_];   // 32 KB (0/1 bytes, all 8 batches)
    int t   = blockIdx.x;
    int tid = threadIdx.x;

#pragma unroll
    for (int i = 0; i < 8; i++) {
        uint4 u = z[((size_t)i * T_ + t) * (CIN_ / 4) + tid];
        uchar4 c;
        c.x = (u.x != 0u);
        c.y = (u.y != 0u);
        c.z = (u.z != 0u);
        c.w = (u.w != 0u);
        ((uchar4*)zs)[i * 1024 + tid] = c;
        float4 f;
        f.x = c.x ? 1.0f : 0.0f;
        f.y = c.y ? 1.0f : 0.0f;
        f.z = c.z ? 1.0f : 0.0f;
        f.w = c.w ? 1.0f : 0.0f;
        ((float4*)(out + ((size_t)i * T_ + t) * (CIN_ + CH_)))[tid] = f;
    }

    int a[12];
#pragma unroll
    for (int j = 0; j < 12; j++) a[j] = g_in_idx[12 * tid + j];

    __syncthreads();

#pragma unroll 1
    for (int b = 0; b < B_; b++) {
        const unsigned char* zb = zs + b * CIN_;
        uchar4 r;
        r.x = (unsigned char)(zb[a[0]] | zb[a[1]]  | zb[a[2]]);
        r.y = (unsigned char)(zb[a[3]] | zb[a[4]]  | zb[a[5]]);
        r.z = (unsigned char)(zb[a[6]] | zb[a[7]]  | zb[a[8]]);
        r.w = (unsigned char)(zb[a[9]] | zb[a[10]] | zb[a[11]]);
        ((uchar4*)(g_inor + ((size_t)b * T_ + t) * CH_))[tid] = r;
    }
}

// ---------------------------------------------------------------------------
// K3: sequential scan. One block per batch (8 blocks x 1024 threads).
// h kept bit-packed (128 words) replicated 32x bank-interleaved in smem:
//   rep[word*32 + lane] -> bank == lane -> conflict-free random gathers.
// input_or consumed as coalesced bytes (4/thread/step, prefetched).
// ---------------------------------------------------------------------------
__global__ void __launch_bounds__(1024) scan_kernel(const unsigned* __restrict__ h0)
{
    __shared__ unsigned rep[2][NW_ * 32];   // 2 x 16 KB, double-buffered
    int b    = blockIdx.x;
    int tid  = threadIdx.x;
    int lane = tid & 31;
    int wid  = tid >> 5;

    // This thread owns dests d = c*1024 + tid (c = 0..3).
    unsigned off0[4], off1[4], off2[4];
    unsigned sh0[4],  sh1[4],  sh2[4];
#pragma unroll
    for (int c = 0; c < 4; c++) {
        int d  = c * 1024 + tid;
        int s0 = g_hid_idx[3 * d], s1 = g_hid_idx[3 * d + 1], s2 = g_hid_idx[3 * d + 2];
        off0[c] = (unsigned)((s0 >> 5) * 32 + lane);  sh0[c] = (unsigned)(s0 & 31);
        off1[c] = (unsigned)((s1 >> 5) * 32 + lane);  sh1[c] = (unsigned)(s1 & 31);
        off2[c] = (unsigned)((s2 >> 5) * 32 + lane);  sh2[c] = (unsigned)(s2 & 31);
    }

    // h(-1) = h0 (0/1 words, any dtype), bit-packed + replicated.
    const unsigned* hb = h0 + (size_t)b * CH_;
#pragma unroll
    for (int c = 0; c < 4; c++) {
        unsigned w = __ballot_sync(0xffffffffu, hb[c * 1024 + tid] != 0u);
        rep[0][(c * 32 + wid) * 32 + lane] = w;
    }

    const unsigned char* inb  = g_inor + (size_t)b * T_ * CH_;
    unsigned*            hout = g_hsp  + (size_t)b * T_ * NW_;

    // Input bytes for t = 0 (coalesced: consecutive tid -> consecutive bytes).
    unsigned char cb0 = inb[       tid];
    unsigned char cb1 = inb[1024 + tid];
    unsigned char cb2 = inb[2048 + tid];
    unsigned char cb3 = inb[3072 + tid];
    __syncthreads();

    int p = 0;
#pragma unroll 1
    for (int t = 0; t < T_; t++) {
        // Prefetch input bytes for t+1 (hides L2 latency under the step).
        unsigned char nb0 = 0, nb1 = 0, nb2 = 0, nb3 = 0;
        if (t + 1 < T_) {
            const unsigned char* nr = inb + (size_t)(t + 1) * CH_;
            nb0 = nr[tid]; nb1 = nr[1024 + tid]; nb2 = nr[2048 + tid]; nb3 = nr[3072 + tid];
        }

        const unsigned* cur   = rep[p];
        unsigned*       nextb = rep[p ^ 1];
        unsigned wv0, wv1, wv2, wv3;

#pragma unroll
        for (int c = 0; c < 4; c++) {
            unsigned g0 = cur[off0[c]];                 // conflict-free LDS.32
            unsigned g1 = cur[off1[c]];
            unsigned g2 = cur[off2[c]];
            unsigned orw = (g0 >> sh0[c]) | (g1 >> sh1[c]) | (g2 >> sh2[c]);
            unsigned char cb = (c == 0) ? cb0 : (c == 1) ? cb1 : (c == 2) ? cb2 : cb3;
            bool bit = ((orw & 1u) != 0u) && (cb != 0);
            unsigned w = __ballot_sync(0xffffffffu, bit);
            nextb[(c * 32 + wid) * 32 + lane] = w;      // conflict-free replicate write
            if      (c == 0) wv0 = w;
            else if (c == 1) wv1 = w;
            else if (c == 2) wv2 = w;
            else             wv3 = w;
        }

        // Persist h(t): lanes 0..3 write the 4 words this warp produced.
        unsigned val = (lane == 0) ? wv0 : (lane == 1) ? wv1 : (lane == 2) ? wv2 : wv3;
        if (lane < 4) hout[(size_t)t * NW_ + lane * 32 + wid] = val;

        cb0 = nb0; cb1 = nb1; cb2 = nb2; cb3 = nb3;
        __syncthreads();
        p ^= 1;
    }
}

// ---------------------------------------------------------------------------
// K4: unpack h_seq bits -> float 0/1 into the output (cols CIN_..CIN_+CH_).
// One thread per 4 output floats (float4 store).
// ---------------------------------------------------------------------------
__global__ void __launch_bounds__(256) unpack_kernel(float* __restrict__ out)
{
    unsigned idx = blockIdx.x * 256u + threadIdx.x;   // over B*T*CH/4 = 8.4M
    unsigned i4  = idx & 1023u;                       // quad index within row
    unsigned bt  = idx >> 10;                         // b*T + t
    unsigned w   = g_hsp[(size_t)bt * NW_ + (i4 >> 3)];
    unsigned sh  = (i4 & 7u) * 4u;
    float4 v;
    v.x = ((w >> (sh + 0)) & 1u) ? 1.0f : 0.0f;
    v.y = ((w >> (sh + 1)) & 1u) ? 1.0f : 0.0f;
    v.z = ((w >> (sh + 2)) & 1u) ? 1.0f : 0.0f;
    v.w = ((w >> (sh + 3)) & 1u) ? 1.0f : 0.0f;
    ((float4*)(out + (size_t)bt * (CIN_ + CH_) + CIN_))[i4] = v;
}

// ---------------------------------------------------------------------------
// Launch. z and h0 identified by unique element counts; the two A matrices
// (equal size) keep positional order (input before hidden).
// ---------------------------------------------------------------------------
extern "C" void kernel_launch(void* const* d_in, const int* in_sizes, int n_in,
                              void* d_out, int out_size)
{
    const void* z   = nullptr;   // (B,T,CIN)  33,554,432 elems
    const void* h0  = nullptr;   // (B,CH)         32,768 elems
    const void* Ain = nullptr;   // (CH,CIN)   16,777,216 elems
    const void* Ahd = nullptr;   // (CH,CH)    16,777,216 elems

    for (int i = 0; i < n_in; i++) {
        long long sz = in_sizes[i];
        if      (sz == (long long)B_ * T_ * CIN_) z  = d_in[i];
        else if (sz == (long long)B_ * CH_)       h0 = d_in[i];
        else if (!Ain)                            Ain = d_in[i];
        else if (!Ahd)                            Ahd = d_in[i];
    }
    if (!z || !h0 || !Ain || !Ahd) {   // fallback: declared order
        z   = d_in[0];
        h0  = d_in[1];
        Ain = d_in[2];
        Ahd = d_in[3];
    }

    float* out = (float*)d_out;   // (B,T,CIN+CH) float 0/1

    extract_idx_kernel<<<1024, 256>>>((const unsigned*)Ain, (const unsigned*)Ahd);
    input_or_kernel<<<T_, 1024>>>((const uint4*)z, out);
    scan_kernel<<<B_, 1024>>>((const unsigned*)h0);
    unpack_kernel<<<(B_ * T_ * CH_ / 4) / 256, 256>>>(out);
}

// round 10
// speedup vs baseline: 1.3969x; 1.3969x over previous
#include <cuda_runtime.h>
#include <cstdint>

// Problem constants (fixed by the dataset)
#define B_   8
#define T_   1024
#define CIN_ 4096
#define CH_  4096
#define NW_  (CH_/32)      // 128 words per hidden state

// Scratch (device globals: no allocation allowed)
__device__ int      g_in_idx [CH_ * 3];            // fan-in of input graph
__device__ int      g_hid_idx[CH_ * 3];            // fan-in of hidden graph
__device__ unsigned g_inorp[B_ * T_ * NW_];        // 4 MB bit-packed input_or
                                                   // layout: [b][t][wid][c]  (c fastest)
__device__ unsigned g_hsp  [B_ * T_ * NW_];        // 4 MB bit-packed h sequence
                                                   // layout: [b][t/4][word][t%4]

// ---------------------------------------------------------------------------
// K1: extract the 3 nonzero column indices per row. One WARP per row,
// ballot + ffs compaction. Nonzero test on the raw 32-bit WORD (dtype-proof:
// works for float32 1.0f and int32/bool-word 1).
// ---------------------------------------------------------------------------
__global__ void __launch_bounds__(256) extract_idx_kernel(
    const unsigned* __restrict__ Ain, const unsigned* __restrict__ Ahid)
{
    int wg   = (blockIdx.x * 256 + threadIdx.x) >> 5;
    int lane = threadIdx.x & 31;

    const unsigned* row;
    int* outp;
    if (wg < CH_) { row = Ain  + (size_t)wg * CIN_;         outp = g_in_idx  + 3 * wg; }
    else          { row = Ahid + (size_t)(wg - CH_) * CH_;  outp = g_hid_idx + 3 * (wg - CH_); }

    int cnt = 0;
#pragma unroll 4
    for (int base = 0; base < CIN_; base += 32) {
        unsigned v = row[base + lane];
        unsigned m = __ballot_sync(0xffffffffu, v != 0u);
        while (m != 0u && cnt < 3) {
            int bit = __ffs(m) - 1;
            if (lane == 0) outp[cnt] = base + bit;
            cnt++;
            m &= m - 1u;
        }
        if (cnt >= 3) break;   // cnt is warp-uniform
    }
}

// ---------------------------------------------------------------------------
// K2: per time step t (grid = T_ blocks, 1024 threads):
//   (a) write z into the output as explicit 1.0f/0.0f floats
//   (b) stage z as 0/1 BYTES in smem
//   (c) per chunk c, dest i = c*1024 + tid: bit = z[a0]|z[a1]|z[a2],
//       ballot -> word, packed warp-contiguous: orow[wid*4 + c].
// ---------------------------------------------------------------------------
__global__ void __launch_bounds__(1024) input_or_kernel(
    const uint4* __restrict__ z, float* __restrict__ out)
{
    __shared__ unsigned char zs[B_ * CIN_];   // 32 KB (0/1 bytes, all 8 batches)
    int t    = blockIdx.x;
    int tid  = threadIdx.x;
    int lane = tid & 31;
    int wid  = tid >> 5;

#pragma unroll
    for (int i = 0; i < 8; i++) {
        uint4 u = z[((size_t)i * T_ + t) * (CIN_ / 4) + tid];
        uchar4 c;
        c.x = (u.x != 0u);
        c.y = (u.y != 0u);
        c.z = (u.z != 0u);
        c.w = (u.w != 0u);
        ((uchar4*)zs)[i * 1024 + tid] = c;
        float4 f;
        f.x = c.x ? 1.0f : 0.0f;
        f.y = c.y ? 1.0f : 0.0f;
        f.z = c.z ? 1.0f : 0.0f;
        f.w = c.w ? 1.0f : 0.0f;
        ((float4*)(out + ((size_t)i * T_ + t) * (CIN_ + CH_)))[tid] = f;
    }

    // Fan-in indices for dests c*1024 + tid, c = 0..3.
    int a0[4], a1[4], a2[4];
#pragma unroll
    for (int c = 0; c < 4; c++) {
        int i = c * 1024 + tid;
        a0[c] = g_in_idx[3 * i];
        a1[c] = g_in_idx[3 * i + 1];
        a2[c] = g_in_idx[3 * i + 2];
    }
    __syncthreads();

#pragma unroll 1
    for (int b = 0; b < B_; b++) {
        const unsigned char* zb = zs + b * CIN_;
        unsigned w[4];
#pragma unroll
        for (int c = 0; c < 4; c++) {
            unsigned v = (unsigned)(zb[a0[c]] | zb[a1[c]] | zb[a2[c]]);
            w[c] = __ballot_sync(0xffffffffu, v != 0u);
        }
        if (lane == 0) {
            uint4 pw = make_uint4(w[0], w[1], w[2], w[3]);
            ((uint4*)(g_inorp + ((size_t)b * T_ + t) * NW_))[wid] = pw;
        }
    }
}

// ---------------------------------------------------------------------------
// K3: sequential scan. One block per batch (8 blocks x 1024 threads).
// h bit-packed (128 words) replicated 32x bank-interleaved in smem:
//   rep[word*32 + lane] -> bank == lane -> conflict-free random gathers.
// input_or consumed as ONE uniform LDG.128 per thread per step (prefetched).
// h(t) words accumulated in registers over 4 steps -> one STG.128.
// ---------------------------------------------------------------------------
__global__ void __launch_bounds__(1024) scan_kernel(const unsigned* __restrict__ h0)
{
    __shared__ unsigned rep[2][NW_ * 32];   // 2 x 16 KB, double-buffered
    int b    = blockIdx.x;
    int tid  = threadIdx.x;
    int lane = tid & 31;
    int wid  = tid >> 5;

    // This thread owns dests d = c*1024 + tid (c = 0..3).
    unsigned off0[4], off1[4], off2[4];
    unsigned sh0[4],  sh1[4],  sh2[4];
#pragma unroll
    for (int c = 0; c < 4; c++) {
        int d  = c * 1024 + tid;
        int s0 = g_hid_idx[3 * d], s1 = g_hid_idx[3 * d + 1], s2 = g_hid_idx[3 * d + 2];
        off0[c] = (unsigned)((s0 >> 5) * 32 + lane);  sh0[c] = (unsigned)(s0 & 31);
        off1[c] = (unsigned)((s1 >> 5) * 32 + lane);  sh1[c] = (unsigned)(s1 & 31);
        off2[c] = (unsigned)((s2 >> 5) * 32 + lane);  sh2[c] = (unsigned)(s2 & 31);
    }

    // h(-1) = h0 (0/1 words, any dtype), bit-packed + replicated.
    const unsigned* hb = h0 + (size_t)b * CH_;
#pragma unroll
    for (int c = 0; c < 4; c++) {
        unsigned w = __ballot_sync(0xffffffffu, hb[c * 1024 + tid] != 0u);
        rep[0][(c * 32 + wid) * 32 + lane] = w;
    }

    const uint4* inb  = (const uint4*)(g_inorp + (size_t)b * T_ * NW_);  // 32 uint4 / t
    uint4*       hout = (uint4*)(g_hsp + (size_t)b * T_ * NW_);          // [tq][word]

    uint4 iw = inb[wid];          // uniform per warp: words for chunks 0..3 at t=0
    __syncthreads();

    int p = 0;
#pragma unroll 1
    for (int tq = 0; tq < T_ / 4; tq++) {
        unsigned wh0 = 0, wh1 = 0, wh2 = 0, wh3 = 0;
#pragma unroll
        for (int j = 0; j < 4; j++) {
            int t = tq * 4 + j;
            // Prefetch input words for t+1 (uniform LDG.128, L2-resident).
            uint4 nx = make_uint4(0u, 0u, 0u, 0u);
            if (t + 1 < T_) nx = inb[(t + 1) * 32 + wid];

            const unsigned* cur   = rep[p];
            unsigned*       nextb = rep[p ^ 1];
            unsigned val = 0;

#pragma unroll
            for (int c = 0; c < 4; c++) {
                unsigned g0 = cur[off0[c]];                 // conflict-free LDS.32
                unsigned g1 = cur[off1[c]];
                unsigned g2 = cur[off2[c]];
                unsigned orw = (g0 >> sh0[c]) | (g1 >> sh1[c]) | (g2 >> sh2[c]);
                unsigned inw = (c == 0) ? iw.x : (c == 1) ? iw.y : (c == 2) ? iw.z : iw.w;
                bool bit = ((orw & (inw >> lane)) & 1u) != 0u;
                unsigned w = __ballot_sync(0xffffffffu, bit);
                nextb[(c * 32 + wid) * 32 + lane] = w;      // conflict-free replicate
                if (lane == c) val = w;                     // lanes 0..3 keep their word
            }

            if      (j == 0) wh0 = val;
            else if (j == 1) wh1 = val;
            else if (j == 2) wh2 = val;
            else             wh3 = val;

            iw = nx;
            __syncthreads();
            p ^= 1;
        }
        // Persist 4 steps of h for this warp's 4 words: lanes 0..3 each hold
        // word (lane*32 + wid) across t = 4tq..4tq+3.  One STG.128.
        if (lane < 4) hout[(size_t)tq * NW_ + lane * 32 + wid] =
            make_uint4(wh0, wh1, wh2, wh3);
    }
}

// ---------------------------------------------------------------------------
// K4: unpack h_seq bits -> float 0/1 into the output (cols CIN_..CIN_+CH_).
// One thread per 4 output floats. g_hsp layout: [b][t/4][word][t%4].
// ---------------------------------------------------------------------------
__global__ void __launch_bounds__(256) unpack_kernel(float* __restrict__ out)
{
    unsigned idx = blockIdx.x * 256u + threadIdx.x;   // over B*T*CH/4 = 8.4M
    unsigned i4  = idx & 1023u;                       // quad index within row
    unsigned bt  = idx >> 10;                         // b*T + t
    unsigned b   = bt >> 10;
    unsigned t   = bt & 1023u;
    unsigned wrd = i4 >> 3;                           // word 0..127
    unsigned w   = g_hsp[(((size_t)b * (T_ / 4) + (t >> 2)) * NW_ + wrd) * 4 + (t & 3u)];
    unsigned sh  = (i4 & 7u) * 4u;
    float4 v;
    v.x = ((w >> (sh + 0)) & 1u) ? 1.0f : 0.0f;
    v.y = ((w >> (sh + 1)) & 1u) ? 1.0f : 0.0f;
    v.z = ((w >> (sh + 2)) & 1u) ? 1.0f : 0.0f;
    v.w = ((w >> (sh + 3)) & 1u) ? 1.0f : 0.0f;
    ((float4*)(out + (size_t)bt * (CIN_ + CH_) + CIN_))[i4] = v;
}

// ---------------------------------------------------------------------------
// Launch. z and h0 identified by unique element counts; the two A matrices
// (equal size) keep positional order (input before hidden).
// ---------------------------------------------------------------------------
extern "C" void kernel_launch(void* const* d_in, const int* in_sizes, int n_in,
                              void* d_out, int out_size)
{
    const void* z   = nullptr;   // (B,T,CIN)  33,554,432 elems
    const void* h0  = nullptr;   // (B,CH)         32,768 elems
    const void* Ain = nullptr;   // (CH,CIN)   16,777,216 elems
    const void* Ahd = nullptr;   // (CH,CH)    16,777,216 elems

    for (int i = 0; i < n_in; i++) {
        long long sz = in_sizes[i];
        if      (sz == (long long)B_ * T_ * CIN_) z  = d_in[i];
        else if (sz == (long long)B_ * CH_)       h0 = d_in[i];
        else if (!Ain)                            Ain = d_in[i];
        else if (!Ahd)                            Ahd = d_in[i];
    }
    if (!z || !h0 || !Ain || !Ahd) {   // fallback: declared order
        z   = d_in[0];
        h0  = d_in[1];
        Ain = d_in[2];
        Ahd = d_in[3];
    }

    float* out = (float*)d_out;   // (B,T,CIN+CH) float 0/1

    extract_idx_kernel<<<1024, 256>>>((const unsigned*)Ain, (const unsigned*)Ahd);
    input_or_kernel<<<T_, 1024>>>((const uint4*)z, out);
    scan_kernel<<<B_, 1024>>>((const unsigned*)h0);
    unpack_kernel<<<(B_ * T_ * CH_ / 4) / 256, 256>>>(out);
}

// round 14
// speedup vs baseline: 1.4160x; 1.0136x over previous
#include <cuda_runtime.h>
#include <cstdint>

// Problem constants (fixed by the dataset)
#define B_   8
#define T_   1024
#define CIN_ 4096
#define CH_  4096
#define NW_  (CH_/32)      // 128 words per hidden state

// Scratch (device globals: no allocation allowed)
__device__ int      g_in_idx [CH_ * 3];            // fan-in of input graph
__device__ int      g_hid_idx[CH_ * 3];            // fan-in of hidden graph
// +NW_ pad: scan prefetches t+1 unconditionally; the pad row is read (and
// discarded) at b=7, t=1023.  Layout: [b][t][wid][c]  (c fastest)
__device__ unsigned g_inorp[(B_ * T_ + 1) * NW_];  // 4 MB bit-packed input_or
__device__ unsigned g_hsp  [B_ * T_ * NW_];        // 4 MB bit-packed h sequence
                                                   // layout: [b][t/4][word][t%4]

// ---------------------------------------------------------------------------
// K1: extract the 3 nonzero column indices per row. One WARP per row,
// ballot + ffs compaction. Nonzero test on the raw 32-bit WORD (dtype-proof:
// works for float32 1.0f and int32/bool-word 1).
// ---------------------------------------------------------------------------
__global__ void __launch_bounds__(256) extract_idx_kernel(
    const unsigned* __restrict__ Ain, const unsigned* __restrict__ Ahid)
{
    int wg   = (blockIdx.x * 256 + threadIdx.x) >> 5;
    int lane = threadIdx.x & 31;

    const unsigned* row;
    int* outp;
    if (wg < CH_) { row = Ain  + (size_t)wg * CIN_;         outp = g_in_idx  + 3 * wg; }
    else          { row = Ahid + (size_t)(wg - CH_) * CH_;  outp = g_hid_idx + 3 * (wg - CH_); }

    int cnt = 0;
#pragma unroll 4
    for (int base = 0; base < CIN_; base += 32) {
        unsigned v = row[base + lane];
        unsigned m = __ballot_sync(0xffffffffu, v != 0u);
        while (m != 0u && cnt < 3) {
            int bit = __ffs(m) - 1;
            if (lane == 0) outp[cnt] = base + bit;
            cnt++;
            m &= m - 1u;
        }
        if (cnt >= 3) break;   // cnt is warp-uniform
    }
}

// ---------------------------------------------------------------------------
// K2: per time step t (grid = T_ blocks, 1024 threads):
//   (a) write z into the output as explicit 1.0f/0.0f floats
//   (b) stage z as 0/1 BYTES in smem
//   (c) per chunk c, dest i = c*1024 + tid: bit = z[a0]|z[a1]|z[a2],
//       ballot -> word, packed warp-contiguous: orow[wid*4 + c].
// ---------------------------------------------------------------------------
__global__ void __launch_bounds__(1024) input_or_kernel(
    const uint4* __restrict__ z, float* __restrict__ out)
{
    __shared__ unsigned char zs[B_ * CIN_];   // 32 KB (0/1 bytes, all 8 batches)
    int t    = blockIdx.x;
    int tid  = threadIdx.x;
    int lane = tid & 31;
    int wid  = tid >> 5;

#pragma unroll
    for (int i = 0; i < 8; i++) {
        uint4 u = z[((size_t)i * T_ + t) * (CIN_ / 4) + tid];
        uchar4 c;
        c.x = (u.x != 0u);
        c.y = (u.y != 0u);
        c.z = (u.z != 0u);
        c.w = (u.w != 0u);
        ((uchar4*)zs)[i * 1024 + tid] = c;
        float4 f;
        f.x = c.x ? 1.0f : 0.0f;
        f.y = c.y ? 1.0f : 0.0f;
        f.z = c.z ? 1.0f : 0.0f;
        f.w = c.w ? 1.0f : 0.0f;
        ((float4*)(out + ((size_t)i * T_ + t) * (CIN_ + CH_)))[tid] = f;
    }

    // Fan-in indices for dests c*1024 + tid, c = 0..3.
    int a0[4], a1[4], a2[4];
#pragma unroll
    for (int c = 0; c < 4; c++) {
        int i = c * 1024 + tid;
        a0[c] = g_in_idx[3 * i];
        a1[c] = g_in_idx[3 * i + 1];
        a2[c] = g_in_idx[3 * i + 2];
    }
    __syncthreads();

#pragma unroll 1
    for (int b = 0; b < B_; b++) {
        const unsigned char* zb = zs + b * CIN_;
        unsigned w[4];
#pragma unroll
        for (int c = 0; c < 4; c++) {
            unsigned v = (unsigned)(zb[a0[c]] | zb[a1[c]] | zb[a2[c]]);
            w[c] = __ballot_sync(0xffffffffu, v != 0u);
        }
        if (lane == 0) {
            uint4 pw = make_uint4(w[0], w[1], w[2], w[3]);
            ((uint4*)(g_inorp + ((size_t)b * T_ + t) * NW_))[wid] = pw;
        }
    }
}

// ---------------------------------------------------------------------------
// K3: sequential scan. One block per batch (8 blocks x 1024 threads).
// h bit-packed (128 words) replicated 32x bank-interleaved in smem:
//   rep[word*32 + lane] -> bank == lane -> conflict-free random gathers.
// input_or consumed as ONE uniform LDG.128 per thread per step, prefetched
// UNCONDITIONALLY (g_inorp is padded). Input AND applied at WORD level after
// the ballot (iw is warp-uniform), shortening the per-lane dependency chain.
// h(t) words accumulated in registers over 4 steps -> one STG.128.
// ---------------------------------------------------------------------------
__global__ void __launch_bounds__(1024) scan_kernel(const unsigned* __restrict__ h0)
{
    __shared__ unsigned rep[2][NW_ * 32];   // 2 x 16 KB, double-buffered
    int b    = blockIdx.x;
    int tid  = threadIdx.x;
    int lane = tid & 31;
    int wid  = tid >> 5;

    // This thread owns dests d = c*1024 + tid (c = 0..3).
    unsigned off0[4], off1[4], off2[4];
    unsigned sh0[4],  sh1[4],  sh2[4];
#pragma unroll
    for (int c = 0; c < 4; c++) {
        int d  = c * 1024 + tid;
        int s0 = g_hid_idx[3 * d], s1 = g_hid_idx[3 * d + 1], s2 = g_hid_idx[3 * d + 2];
        off0[c] = (unsigned)((s0 >> 5) * 32 + lane);  sh0[c] = (unsigned)(s0 & 31);
        off1[c] = (unsigned)((s1 >> 5) * 32 + lane);  sh1[c] = (unsigned)(s1 & 31);
        off2[c] = (unsigned)((s2 >> 5) * 32 + lane);  sh2[c] = (unsigned)(s2 & 31);
    }

    // h(-1) = h0 (0/1 words, any dtype), bit-packed + replicated.
    const unsigned* hb = h0 + (size_t)b * CH_;
#pragma unroll
    for (int c = 0; c < 4; c++) {
        unsigned w = __ballot_sync(0xffffffffu, hb[c * 1024 + tid] != 0u);
        rep[0][(c * 32 + wid) * 32 + lane] = w;
    }

    const uint4* inb  = (const uint4*)(g_inorp + (size_t)b * T_ * NW_);  // 32 uint4 / t
    uint4*       hout = (uint4*)(g_hsp + (size_t)b * T_ * NW_);          // [tq][word]

    uint4 iw = inb[wid];          // uniform per warp: words for chunks 0..3 at t=0
    __syncthreads();

    int p = 0;
#pragma unroll 1
    for (int tq = 0; tq < T_ / 4; tq++) {
        unsigned wh0 = 0, wh1 = 0, wh2 = 0, wh3 = 0;
#pragma unroll
        for (int j = 0; j < 4; j++) {
            int t = tq * 4 + j;
            // Unconditional prefetch of t+1 (pad row read+discarded at the end).
            uint4 nx = inb[(t + 1) * 32 + wid];

            const unsigned* cur   = rep[p];
            unsigned*       nextb = rep[p ^ 1];
            unsigned val = 0;

#pragma unroll
            for (int c = 0; c < 4; c++) {
                unsigned g0 = cur[off0[c]];                 // conflict-free LDS.32
                unsigned g1 = cur[off1[c]];
                unsigned g2 = cur[off2[c]];
                // single LOP3 OR of the three shifted words, bit0 = this dest
                unsigned orw = (g0 >> sh0[c]) | (g1 >> sh1[c]) | (g2 >> sh2[c]);
                unsigned inw = (c == 0) ? iw.x : (c == 1) ? iw.y : (c == 2) ? iw.z : iw.w;
                // input AND applied at word level AFTER ballot (inw warp-uniform)
                unsigned w = __ballot_sync(0xffffffffu, (orw & 1u) != 0u) & inw;
                nextb[(c * 32 + wid) * 32 + lane] = w;      // conflict-free replicate
                if (lane == c) val = w;                     // lanes 0..3 keep their word
            }

            if      (j == 0) wh0 = val;
            else if (j == 1) wh1 = val;
            else if (j == 2) wh2 = val;
            else             wh3 = val;

            iw = nx;
            __syncthreads();
            p ^= 1;
        }
        // Persist 4 steps of h for this warp's 4 words: lanes 0..3 each hold
        // word (lane*32 + wid) across t = 4tq..4tq+3.  One STG.128.
        if (lane < 4) hout[(size_t)tq * NW_ + lane * 32 + wid] =
            make_uint4(wh0, wh1, wh2, wh3);
    }
}

// ---------------------------------------------------------------------------
// K4: unpack h_seq bits -> float 0/1 into the output (cols CIN_..CIN_+CH_).
// One thread per 4 output floats. g_hsp layout: [b][t/4][word][t%4].
// ---------------------------------------------------------------------------
__global__ void __launch_bounds__(256) unpack_kernel(float* __restrict__ out)
{
    unsigned idx = blockIdx.x * 256u + threadIdx.x;   // over B*T*CH/4 = 8.4M
    unsigned i4  = idx & 1023u;                       // quad index within row
    unsigned bt  = idx >> 10;                         // b*T + t
    unsigned b   = bt >> 10;
    unsigned t   = bt & 1023u;
    unsigned wrd = i4 >> 3;                           // word 0..127
    unsigned w   = g_hsp[(((size_t)b * (T_ / 4) + (t >> 2)) * NW_ + wrd) * 4 + (t & 3u)];
    unsigned sh  = (i4 & 7u) * 4u;
    float4 v;
    v.x = ((w >> (sh + 0)) & 1u) ? 1.0f : 0.0f;
    v.y = ((w >> (sh + 1)) & 1u) ? 1.0f : 0.0f;
    v.z = ((w >> (sh + 2)) & 1u) ? 1.0f : 0.0f;
    v.w = ((w >> (sh + 3)) & 1u) ? 1.0f : 0.0f;
    ((float4*)(out + (size_t)bt * (CIN_ + CH_) + CIN_))[i4] = v;
}

// ---------------------------------------------------------------------------
// Launch. z and h0 identified by unique element counts; the two A matrices
// (equal size) keep positional order (input before hidden).
// ---------------------------------------------------------------------------
extern "C" void kernel_launch(void* const* d_in, const int* in_sizes, int n_in,
                              void* d_out, int out_size)
{
    const void* z   = nullptr;   // (B,T,CIN)  33,554,432 elems
    const void* h0  = nullptr;   // (B,CH)         32,768 elems
    const void* Ain = nullptr;   // (CH,CIN)   16,777,216 elems
    const void* Ahd = nullptr;   // (CH,CH)    16,777,216 elems

    for (int i = 0; i < n_in; i++) {
        long long sz = in_sizes[i];
        if      (sz == (long long)B_ * T_ * CIN_) z  = d_in[i];
        else if (sz == (long long)B_ * CH_)       h0 = d_in[i];
        else if (!Ain)                            Ain = d_in[i];
        else if (!Ahd)                            Ahd = d_in[i];
    }
    if (!z || !h0 || !Ain || !Ahd) {   // fallback: declared order
        z   = d_in[0];
        h0  = d_in[1];
        Ain = d_in[2];
        Ahd = d_in[3];
    }

    float* out = (float*)d_out;   // (B,T,CIN+CH) float 0/1

    extract_idx_kernel<<<1024, 256>>>((const unsigned*)Ain, (const unsigned*)Ahd);
    input_or_kernel<<<T_, 1024>>>((const uint4*)z, out);
    scan_kernel<<<B_, 1024>>>((const unsigned*)h0);
    unpack_kernel<<<(B_ * T_ * CH_ / 4) / 256, 256>>>(out);
}